// round 1
// baseline (speedup 1.0000x reference)
#include <cuda_runtime.h>
#include <cuda_bf16.h>
#include <math.h>

// Problem dims
#define BATCH 2
#define SEQ   2048
#define DIM   2048
#define NSTATE 16
#define TOKENS (BATCH*SEQ)        // 4096
#define TWO_DIM (2*DIM)           // 4096
#define LN_EPS 1e-5f

// -------------------- scratch (device globals, allocation-free) ------------
__device__ float g_xn[TOKENS * DIM];        // layernormed x          (32MB)
__device__ float g_xz[TOKENS * TWO_DIM];    // [x_ssm | z]            (64MB)
__device__ float g_dt[TOKENS * DIM];        // dt after softplus/clamp(32MB)
__device__ float g_gated[TOKENS * DIM];     // y * silu(z)            (32MB)
__device__ float g_coef[TOKENS * NSTATE];   // Bm*Cm                  (tiny)

// -------------------- LayerNorm --------------------------------------------
// one block per token, 256 threads, 8 elems/thread
__global__ void __launch_bounds__(256) ln_kernel(
    const float* __restrict__ x,
    const float* __restrict__ gamma,
    const float* __restrict__ beta,
    float* __restrict__ out)
{
    const int token = blockIdx.x;
    const float* xp = x + (size_t)token * DIM;
    float* op = out + (size_t)token * DIM;
    const int base = threadIdx.x * 8;

    float4 a = *(const float4*)(xp + base);
    float4 b = *(const float4*)(xp + base + 4);

    float s  = a.x + a.y + a.z + a.w + b.x + b.y + b.z + b.w;
    float ss = a.x*a.x + a.y*a.y + a.z*a.z + a.w*a.w
             + b.x*b.x + b.y*b.y + b.z*b.z + b.w*b.w;

    // warp reduce
    #pragma unroll
    for (int o = 16; o > 0; o >>= 1) {
        s  += __shfl_down_sync(0xffffffffu, s,  o);
        ss += __shfl_down_sync(0xffffffffu, ss, o);
    }
    __shared__ float sbuf[8], ssbuf[8];
    const int warp = threadIdx.x >> 5, lane = threadIdx.x & 31;
    if (lane == 0) { sbuf[warp] = s; ssbuf[warp] = ss; }
    __syncthreads();
    __shared__ float s_mean, s_rstd;
    if (threadIdx.x == 0) {
        float ts = 0.f, tss = 0.f;
        #pragma unroll
        for (int w = 0; w < 8; w++) { ts += sbuf[w]; tss += ssbuf[w]; }
        float mean = ts * (1.0f / DIM);
        float var  = tss * (1.0f / DIM) - mean * mean;
        s_mean = mean;
        s_rstd = rsqrtf(var + LN_EPS);
    }
    __syncthreads();
    const float mean = s_mean, rstd = s_rstd;

    float4 g0 = *(const float4*)(gamma + base);
    float4 g1 = *(const float4*)(gamma + base + 4);
    float4 bt0 = *(const float4*)(beta + base);
    float4 bt1 = *(const float4*)(beta + base + 4);

    float4 o0, o1;
    o0.x = (a.x - mean) * rstd * g0.x + bt0.x;
    o0.y = (a.y - mean) * rstd * g0.y + bt0.y;
    o0.z = (a.z - mean) * rstd * g0.z + bt0.z;
    o0.w = (a.w - mean) * rstd * g0.w + bt0.w;
    o1.x = (b.x - mean) * rstd * g1.x + bt1.x;
    o1.y = (b.y - mean) * rstd * g1.y + bt1.y;
    o1.z = (b.z - mean) * rstd * g1.z + bt1.z;
    o1.w = (b.w - mean) * rstd * g1.w + bt1.w;
    *(float4*)(op + base)     = o0;
    *(float4*)(op + base + 4) = o1;
}

// -------------------- SGEMM (C = A @ B^T + bias [+epi]) ---------------------
// A: M x K row-major (lda), B: N x K row-major (ldb), C: M x N (ldc).
// 128x128 block tile, BK=16, 256 threads, 8x8 per-thread tile.
// EPI: 0 = bias only; 1 = min(softplus(v),1); 2 = bias + residual
template<int EPI>
__global__ void __launch_bounds__(256, 2) sgemm_nt(
    const float* __restrict__ A, int lda,
    const float* __restrict__ B, int ldb,
    const float* __restrict__ bias,
    const float* __restrict__ res, int ldres,
    float* __restrict__ C, int ldc,
    int K)
{
    __shared__ float As[16][132];
    __shared__ float Bs[16][132];

    const int bm = blockIdx.y * 128;
    const int bn = blockIdx.x * 128;
    const int tid = threadIdx.x;
    const int lr = tid >> 2;           // 0..63
    const int lc = (tid & 3) << 2;     // 0,4,8,12
    const int tx = tid & 15;
    const int ty = tid >> 4;

    const float* Ap = A + (size_t)(bm + lr) * lda + lc;
    const float* Bp = B + (size_t)(bn + lr) * ldb + lc;

    float acc[8][8];
    #pragma unroll
    for (int i = 0; i < 8; i++)
        #pragma unroll
        for (int j = 0; j < 8; j++) acc[i][j] = 0.f;

    for (int k0 = 0; k0 < K; k0 += 16) {
        float4 a0 = *(const float4*)(Ap);
        float4 a1 = *(const float4*)(Ap + (size_t)64 * lda);
        float4 b0 = *(const float4*)(Bp);
        float4 b1 = *(const float4*)(Bp + (size_t)64 * ldb);

        As[lc + 0][lr]      = a0.x;
        As[lc + 1][lr]      = a0.y;
        As[lc + 2][lr]      = a0.z;
        As[lc + 3][lr]      = a0.w;
        As[lc + 0][lr + 64] = a1.x;
        As[lc + 1][lr + 64] = a1.y;
        As[lc + 2][lr + 64] = a1.z;
        As[lc + 3][lr + 64] = a1.w;

        Bs[lc + 0][lr]      = b0.x;
        Bs[lc + 1][lr]      = b0.y;
        Bs[lc + 2][lr]      = b0.z;
        Bs[lc + 3][lr]      = b0.w;
        Bs[lc + 0][lr + 64] = b1.x;
        Bs[lc + 1][lr + 64] = b1.y;
        Bs[lc + 2][lr + 64] = b1.z;
        Bs[lc + 3][lr + 64] = b1.w;

        __syncthreads();

        #pragma unroll
        for (int kk = 0; kk < 16; kk++) {
            float4 ar0 = *(const float4*)&As[kk][ty * 8];
            float4 ar1 = *(const float4*)&As[kk][ty * 8 + 4];
            float4 br0 = *(const float4*)&Bs[kk][tx * 8];
            float4 br1 = *(const float4*)&Bs[kk][tx * 8 + 4];
            float ar[8] = {ar0.x, ar0.y, ar0.z, ar0.w, ar1.x, ar1.y, ar1.z, ar1.w};
            float br[8] = {br0.x, br0.y, br0.z, br0.w, br1.x, br1.y, br1.z, br1.w};
            #pragma unroll
            for (int i = 0; i < 8; i++)
                #pragma unroll
                for (int j = 0; j < 8; j++)
                    acc[i][j] = fmaf(ar[i], br[j], acc[i][j]);
        }
        __syncthreads();
        Ap += 16;
        Bp += 16;
    }

    #pragma unroll
    for (int i = 0; i < 8; i++) {
        const int row = bm + ty * 8 + i;
        #pragma unroll
        for (int j = 0; j < 8; j++) {
            const int col = bn + tx * 8 + j;
            float v = acc[i][j] + bias[col];
            if (EPI == 1) {
                v = (v > 20.f) ? v : log1pf(__expf(v));
                v = fminf(v, 1.0f);
            } else if (EPI == 2) {
                v += res[(size_t)row * ldres + col];
            }
            C[(size_t)row * ldc + col] = v;
        }
    }
}

// -------------------- B / C projection + coef -------------------------------
// coef[t][n] = (x_ssm[t] . W_B[n] + b_B[n]) * (x_ssm[t] . W_C[n] + b_C[n])
// one block per token; 8 warps, each warp handles 2 n-values (B and C dots)
__global__ void __launch_bounds__(256) bc_kernel(
    const float* __restrict__ xz, int ld,
    const float* __restrict__ W_B, const float* __restrict__ b_B,
    const float* __restrict__ W_C, const float* __restrict__ b_C,
    float* __restrict__ coef)
{
    const int token = blockIdx.x;
    const float* xs = xz + (size_t)token * ld;   // x_ssm = first DIM cols
    const int warp = threadIdx.x >> 5, lane = threadIdx.x & 31;
    const int n0 = warp * 2, n1 = warp * 2 + 1;

    const float* wb0 = W_B + (size_t)n0 * DIM;
    const float* wb1 = W_B + (size_t)n1 * DIM;
    const float* wc0 = W_C + (size_t)n0 * DIM;
    const float* wc1 = W_C + (size_t)n1 * DIM;

    float sB0 = 0.f, sB1 = 0.f, sC0 = 0.f, sC1 = 0.f;
    for (int d = lane * 4; d < DIM; d += 32 * 4) {
        float4 xv = *(const float4*)(xs + d);
        float4 vb0 = *(const float4*)(wb0 + d);
        float4 vb1 = *(const float4*)(wb1 + d);
        float4 vc0 = *(const float4*)(wc0 + d);
        float4 vc1 = *(const float4*)(wc1 + d);
        sB0 += xv.x*vb0.x + xv.y*vb0.y + xv.z*vb0.z + xv.w*vb0.w;
        sB1 += xv.x*vb1.x + xv.y*vb1.y + xv.z*vb1.z + xv.w*vb1.w;
        sC0 += xv.x*vc0.x + xv.y*vc0.y + xv.z*vc0.z + xv.w*vc0.w;
        sC1 += xv.x*vc1.x + xv.y*vc1.y + xv.z*vc1.z + xv.w*vc1.w;
    }
    #pragma unroll
    for (int o = 16; o > 0; o >>= 1) {
        sB0 += __shfl_down_sync(0xffffffffu, sB0, o);
        sB1 += __shfl_down_sync(0xffffffffu, sB1, o);
        sC0 += __shfl_down_sync(0xffffffffu, sC0, o);
        sC1 += __shfl_down_sync(0xffffffffu, sC1, o);
    }
    if (lane == 0) {
        float B0 = sB0 + b_B[n0], C0 = sC0 + b_C[n0];
        float B1 = sB1 + b_B[n1], C1 = sC1 + b_C[n1];
        coef[token * NSTATE + n0] = B0 * C0;
        coef[token * NSTATE + n1] = B1 * C1;
    }
}

// -------------------- fused SSM scan + gate ---------------------------------
// gated[t][d] = (sum_n coef[t][n]*exp(A[n][d]*dt[t][d])) * x_ssm[t][d] * silu(z[t][d])
__global__ void __launch_bounds__(256) ssm_kernel(
    const float* __restrict__ xz, int ld,
    const float* __restrict__ dt,
    const float* __restrict__ coef,
    const float* __restrict__ A,   // (NSTATE, DIM)
    float* __restrict__ gated)
{
    const int token = blockIdx.x;
    __shared__ float c[NSTATE];
    if (threadIdx.x < NSTATE) c[threadIdx.x] = coef[token * NSTATE + threadIdx.x];
    __syncthreads();

    const float* xs  = xz + (size_t)token * ld;
    const float* zp  = xs + DIM;
    const float* dtp = dt + (size_t)token * DIM;
    float* gp = gated + (size_t)token * DIM;

    for (int d = threadIdx.x; d < DIM; d += 256) {
        const float dtd = dtp[d];
        float s = 0.f;
        #pragma unroll
        for (int n = 0; n < NSTATE; n++)
            s += c[n] * __expf(A[n * DIM + d] * dtd);
        const float xv = xs[d];
        const float zv = zp[d];
        const float sig = 1.0f / (1.0f + __expf(-zv));
        gp[d] = s * xv * zv * sig;
    }
}

// -------------------- launch ------------------------------------------------
extern "C" void kernel_launch(void* const* d_in, const int* in_sizes, int n_in,
                              void* d_out, int out_size)
{
    const float* x        = (const float*)d_in[0];
    const float* ln_gamma = (const float*)d_in[1];
    const float* ln_beta  = (const float*)d_in[2];
    const float* W_in     = (const float*)d_in[3];
    const float* b_in     = (const float*)d_in[4];
    const float* state_A  = (const float*)d_in[5];
    const float* W_B      = (const float*)d_in[6];
    const float* b_B      = (const float*)d_in[7];
    const float* W_C      = (const float*)d_in[8];
    const float* b_C      = (const float*)d_in[9];
    const float* W_dt     = (const float*)d_in[10];
    const float* b_dt     = (const float*)d_in[11];
    const float* W_out    = (const float*)d_in[12];
    const float* b_out    = (const float*)d_in[13];
    float* out = (float*)d_out;

    float *xn, *xz, *dt, *gated, *coef;
    cudaGetSymbolAddress((void**)&xn,    g_xn);
    cudaGetSymbolAddress((void**)&xz,    g_xz);
    cudaGetSymbolAddress((void**)&dt,    g_dt);
    cudaGetSymbolAddress((void**)&gated, g_gated);
    cudaGetSymbolAddress((void**)&coef,  g_coef);

    // 1. LayerNorm
    ln_kernel<<<TOKENS, 256>>>(x, ln_gamma, ln_beta, xn);

    // 2. xz = xn @ W_in^T + b_in      (M=4096, N=4096, K=2048)
    sgemm_nt<0><<<dim3(TWO_DIM / 128, TOKENS / 128), 256>>>(
        xn, DIM, W_in, DIM, b_in, nullptr, 0, xz, TWO_DIM, DIM);

    // 3. dt = min(softplus(x_ssm @ W_dt^T + b_dt), 1)   (M=4096, N=2048, K=2048)
    sgemm_nt<1><<<dim3(DIM / 128, TOKENS / 128), 256>>>(
        xz, TWO_DIM, W_dt, DIM, b_dt, nullptr, 0, dt, DIM, DIM);

    // 4. coef = (x_ssm@W_B^T + b_B) * (x_ssm@W_C^T + b_C)
    bc_kernel<<<TOKENS, 256>>>(xz, TWO_DIM, W_B, b_B, W_C, b_C, coef);

    // 5. gated = (sum_n coef*exp(A*dt)) * x_ssm * silu(z)
    ssm_kernel<<<TOKENS, 256>>>(xz, TWO_DIM, dt, coef, state_A, gated);

    // 6. out = gated @ W_out^T + b_out + residual(x)
    sgemm_nt<2><<<dim3(DIM / 128, TOKENS / 128), 256>>>(
        gated, DIM, W_out, DIM, b_out, x, DIM, out, DIM, DIM);
}

// round 2
// speedup vs baseline: 2.7929x; 2.7929x over previous
#include <cuda_runtime.h>
#include <cuda_bf16.h>
#include <math.h>

// Problem dims
#define BATCH 2
#define SEQ   2048
#define DIM   2048
#define NSTATE 16
#define TOKENS (BATCH*SEQ)        // 4096
#define TWO_DIM (2*DIM)           // 4096
#define LN_EPS 1e-5f

// -------------------- scratch (device globals, allocation-free) ------------
__device__ float g_xn[TOKENS * DIM];        // layernormed x (tf32-rounded)
__device__ float g_xz[TOKENS * TWO_DIM];    // [x_ssm | z]   (tf32-rounded)
__device__ float g_dt[TOKENS * DIM];        // dt (fp32)
__device__ float g_gated[TOKENS * DIM];     // y*silu(z) (tf32-rounded)
__device__ float g_coef[TOKENS * NSTATE];
__device__ float g_win [TWO_DIM * DIM];     // tf32-rounded weights
__device__ float g_wdt [DIM * DIM];
__device__ float g_wout[DIM * DIM];

// -------------------- helpers ----------------------------------------------
__device__ __forceinline__ float to_tf32(float x) {
    float y;
    asm("cvt.rna.tf32.f32 %0, %1;" : "=f"(y) : "f"(x));
    return y;
}

__device__ __forceinline__ void cp_async16(void* smem, const void* gmem) {
    unsigned s = (unsigned)__cvta_generic_to_shared(smem);
    asm volatile("cp.async.cg.shared.global [%0], [%1], 16;\n" :: "r"(s), "l"(gmem));
}

__device__ __forceinline__ void mma_tf32(float* c, const unsigned* a, const unsigned* b) {
    asm volatile(
        "mma.sync.aligned.m16n8k8.row.col.f32.tf32.tf32.f32 "
        "{%0,%1,%2,%3}, {%4,%5,%6,%7}, {%8,%9}, {%0,%1,%2,%3};"
        : "+f"(c[0]), "+f"(c[1]), "+f"(c[2]), "+f"(c[3])
        : "r"(a[0]), "r"(a[1]), "r"(a[2]), "r"(a[3]), "r"(b[0]), "r"(b[1]));
}

// -------------------- weight tf32 rounding ---------------------------------
__global__ void __launch_bounds__(256) round_kernel(
    const float4* __restrict__ src, float4* __restrict__ dst, int n4)
{
    int i = blockIdx.x * blockDim.x + threadIdx.x;
    int stride = gridDim.x * blockDim.x;
    for (; i < n4; i += stride) {
        float4 v = src[i];
        v.x = to_tf32(v.x); v.y = to_tf32(v.y);
        v.z = to_tf32(v.z); v.w = to_tf32(v.w);
        dst[i] = v;
    }
}

// -------------------- LayerNorm (tf32-rounded output) -----------------------
__global__ void __launch_bounds__(256) ln_kernel(
    const float* __restrict__ x,
    const float* __restrict__ gamma,
    const float* __restrict__ beta,
    float* __restrict__ out)
{
    const int token = blockIdx.x;
    const float* xp = x + (size_t)token * DIM;
    float* op = out + (size_t)token * DIM;
    const int base = threadIdx.x * 8;

    float4 a = *(const float4*)(xp + base);
    float4 b = *(const float4*)(xp + base + 4);

    float s  = a.x + a.y + a.z + a.w + b.x + b.y + b.z + b.w;
    float ss = a.x*a.x + a.y*a.y + a.z*a.z + a.w*a.w
             + b.x*b.x + b.y*b.y + b.z*b.z + b.w*b.w;

    #pragma unroll
    for (int o = 16; o > 0; o >>= 1) {
        s  += __shfl_down_sync(0xffffffffu, s,  o);
        ss += __shfl_down_sync(0xffffffffu, ss, o);
    }
    __shared__ float sbuf[8], ssbuf[8];
    const int warp = threadIdx.x >> 5, lane = threadIdx.x & 31;
    if (lane == 0) { sbuf[warp] = s; ssbuf[warp] = ss; }
    __syncthreads();
    __shared__ float s_mean, s_rstd;
    if (threadIdx.x == 0) {
        float ts = 0.f, tss = 0.f;
        #pragma unroll
        for (int w = 0; w < 8; w++) { ts += sbuf[w]; tss += ssbuf[w]; }
        float mean = ts * (1.0f / DIM);
        float var  = tss * (1.0f / DIM) - mean * mean;
        s_mean = mean;
        s_rstd = rsqrtf(var + LN_EPS);
    }
    __syncthreads();
    const float mean = s_mean, rstd = s_rstd;

    float4 g0 = *(const float4*)(gamma + base);
    float4 g1 = *(const float4*)(gamma + base + 4);
    float4 bt0 = *(const float4*)(beta + base);
    float4 bt1 = *(const float4*)(beta + base + 4);

    float4 o0, o1;
    o0.x = to_tf32((a.x - mean) * rstd * g0.x + bt0.x);
    o0.y = to_tf32((a.y - mean) * rstd * g0.y + bt0.y);
    o0.z = to_tf32((a.z - mean) * rstd * g0.z + bt0.z);
    o0.w = to_tf32((a.w - mean) * rstd * g0.w + bt0.w);
    o1.x = to_tf32((b.x - mean) * rstd * g1.x + bt1.x);
    o1.y = to_tf32((b.y - mean) * rstd * g1.y + bt1.y);
    o1.z = to_tf32((b.z - mean) * rstd * g1.z + bt1.z);
    o1.w = to_tf32((b.w - mean) * rstd * g1.w + bt1.w);
    *(float4*)(op + base)     = o0;
    *(float4*)(op + base + 4) = o1;
}

// -------------------- TF32 tensor-core GEMM (C = A @ B^T + bias [+epi]) -----
// A: MxK row-major (lda), B: NxK row-major (ldb)  ->  mma row.col directly.
// Block tile 128x128, BK=16, 256 threads, warp tile 64x32.
// EPI: 0 = bias; 1 = min(softplus(v),1); 2 = bias + residual
// RND: round output to tf32
#define BM 128
#define BN 128
#define BK 16
#define SPAD 20   // row stride (floats) for smem tiles; conflict-free (20g+t bijective mod 32)

template<int EPI, int RND>
__global__ void __launch_bounds__(256, 2) gemm_tf32(
    const float* __restrict__ A, int lda,
    const float* __restrict__ B, int ldb,
    const float* __restrict__ bias,
    const float* __restrict__ res, int ldres,
    float* __restrict__ C, int ldc,
    int K)
{
    __shared__ float As[2][BM][SPAD];
    __shared__ float Bs[2][BN][SPAD];

    const int bm = blockIdx.y * BM;
    const int bn = blockIdx.x * BN;
    const int tid = threadIdx.x;
    const int wid = tid >> 5;
    const int lane = tid & 31;
    const int g = lane >> 2;       // 0..7
    const int t = lane & 3;        // 0..3

    const int warp_m = wid >> 2;   // 0..1
    const int warp_n = wid & 3;    // 0..3
    const int m0 = warp_m * 64;
    const int n0 = warp_n * 32;

    // load mapping: 512 float4 per tile, 2 per thread
    const int lrow = tid >> 2;           // 0..63
    const int lcol = (tid & 3) << 2;     // 0,4,8,12

    const float* Ag = A + (size_t)(bm + lrow) * lda + lcol;
    const float* Bg = B + (size_t)(bn + lrow) * ldb + lcol;

    float acc[4][4][4];
    #pragma unroll
    for (int i = 0; i < 4; i++)
        #pragma unroll
        for (int j = 0; j < 4; j++)
            #pragma unroll
            for (int r = 0; r < 4; r++) acc[i][j][r] = 0.f;

    // prologue: stage 0
    cp_async16(&As[0][lrow][lcol],      Ag);
    cp_async16(&As[0][lrow + 64][lcol], Ag + (size_t)64 * lda);
    cp_async16(&Bs[0][lrow][lcol],      Bg);
    cp_async16(&Bs[0][lrow + 64][lcol], Bg + (size_t)64 * ldb);
    asm volatile("cp.async.commit_group;\n" ::: "memory");

    int s = 0;
    for (int k0 = 0; k0 < K; k0 += BK, s ^= 1) {
        if (k0 + BK < K) {
            const float* Agn = Ag + k0 + BK;
            const float* Bgn = Bg + k0 + BK;
            cp_async16(&As[s ^ 1][lrow][lcol],      Agn);
            cp_async16(&As[s ^ 1][lrow + 64][lcol], Agn + (size_t)64 * lda);
            cp_async16(&Bs[s ^ 1][lrow][lcol],      Bgn);
            cp_async16(&Bs[s ^ 1][lrow + 64][lcol], Bgn + (size_t)64 * ldb);
            asm volatile("cp.async.commit_group;\n" ::: "memory");
            asm volatile("cp.async.wait_group 1;\n" ::: "memory");
        } else {
            asm volatile("cp.async.wait_group 0;\n" ::: "memory");
        }
        __syncthreads();

        #pragma unroll
        for (int kk = 0; kk < BK; kk += 8) {
            unsigned af[4][4], bf[4][2];
            #pragma unroll
            for (int mt = 0; mt < 4; mt++) {
                const int m = m0 + mt * 16;
                af[mt][0] = __float_as_uint(As[s][m + g][kk + t]);
                af[mt][1] = __float_as_uint(As[s][m + g + 8][kk + t]);
                af[mt][2] = __float_as_uint(As[s][m + g][kk + t + 4]);
                af[mt][3] = __float_as_uint(As[s][m + g + 8][kk + t + 4]);
            }
            #pragma unroll
            for (int nt = 0; nt < 4; nt++) {
                const int n = n0 + nt * 8;
                bf[nt][0] = __float_as_uint(Bs[s][n + g][kk + t]);
                bf[nt][1] = __float_as_uint(Bs[s][n + g][kk + t + 4]);
            }
            #pragma unroll
            for (int mt = 0; mt < 4; mt++)
                #pragma unroll
                for (int nt = 0; nt < 4; nt++)
                    mma_tf32(acc[mt][nt], af[mt], bf[nt]);
        }
        __syncthreads();
    }

    // epilogue
    #pragma unroll
    for (int mt = 0; mt < 4; mt++) {
        const int row0 = bm + m0 + mt * 16 + g;
        #pragma unroll
        for (int nt = 0; nt < 4; nt++) {
            const int col = bn + n0 + nt * 8 + 2 * t;
            const float bv0 = bias[col], bv1 = bias[col + 1];
            float v00 = acc[mt][nt][0] + bv0;
            float v01 = acc[mt][nt][1] + bv1;
            float v10 = acc[mt][nt][2] + bv0;
            float v11 = acc[mt][nt][3] + bv1;
            if (EPI == 1) {
                v00 = fminf((v00 > 20.f) ? v00 : log1pf(__expf(v00)), 1.0f);
                v01 = fminf((v01 > 20.f) ? v01 : log1pf(__expf(v01)), 1.0f);
                v10 = fminf((v10 > 20.f) ? v10 : log1pf(__expf(v10)), 1.0f);
                v11 = fminf((v11 > 20.f) ? v11 : log1pf(__expf(v11)), 1.0f);
            } else if (EPI == 2) {
                v00 += res[(size_t)row0 * ldres + col];
                v01 += res[(size_t)row0 * ldres + col + 1];
                v10 += res[(size_t)(row0 + 8) * ldres + col];
                v11 += res[(size_t)(row0 + 8) * ldres + col + 1];
            }
            if (RND) {
                v00 = to_tf32(v00); v01 = to_tf32(v01);
                v10 = to_tf32(v10); v11 = to_tf32(v11);
            }
            float2 lo = make_float2(v00, v01);
            float2 hi = make_float2(v10, v11);
            *(float2*)(C + (size_t)row0 * ldc + col)       = lo;
            *(float2*)(C + (size_t)(row0 + 8) * ldc + col) = hi;
        }
    }
}

// -------------------- B / C projection + coef -------------------------------
__global__ void __launch_bounds__(256) bc_kernel(
    const float* __restrict__ xz, int ld,
    const float* __restrict__ W_B, const float* __restrict__ b_B,
    const float* __restrict__ W_C, const float* __restrict__ b_C,
    float* __restrict__ coef)
{
    const int token = blockIdx.x;
    const float* xs = xz + (size_t)token * ld;
    const int warp = threadIdx.x >> 5, lane = threadIdx.x & 31;
    const int n0 = warp * 2, n1 = warp * 2 + 1;

    const float* wb0 = W_B + (size_t)n0 * DIM;
    const float* wb1 = W_B + (size_t)n1 * DIM;
    const float* wc0 = W_C + (size_t)n0 * DIM;
    const float* wc1 = W_C + (size_t)n1 * DIM;

    float sB0 = 0.f, sB1 = 0.f, sC0 = 0.f, sC1 = 0.f;
    for (int d = lane * 4; d < DIM; d += 32 * 4) {
        float4 xv  = *(const float4*)(xs + d);
        float4 vb0 = *(const float4*)(wb0 + d);
        float4 vb1 = *(const float4*)(wb1 + d);
        float4 vc0 = *(const float4*)(wc0 + d);
        float4 vc1 = *(const float4*)(wc1 + d);
        sB0 += xv.x*vb0.x + xv.y*vb0.y + xv.z*vb0.z + xv.w*vb0.w;
        sB1 += xv.x*vb1.x + xv.y*vb1.y + xv.z*vb1.z + xv.w*vb1.w;
        sC0 += xv.x*vc0.x + xv.y*vc0.y + xv.z*vc0.z + xv.w*vc0.w;
        sC1 += xv.x*vc1.x + xv.y*vc1.y + xv.z*vc1.z + xv.w*vc1.w;
    }
    #pragma unroll
    for (int o = 16; o > 0; o >>= 1) {
        sB0 += __shfl_down_sync(0xffffffffu, sB0, o);
        sB1 += __shfl_down_sync(0xffffffffu, sB1, o);
        sC0 += __shfl_down_sync(0xffffffffu, sC0, o);
        sC1 += __shfl_down_sync(0xffffffffu, sC1, o);
    }
    if (lane == 0) {
        float B0 = sB0 + b_B[n0], C0 = sC0 + b_C[n0];
        float B1 = sB1 + b_B[n1], C1 = sC1 + b_C[n1];
        coef[token * NSTATE + n0] = B0 * C0;
        coef[token * NSTATE + n1] = B1 * C1;
    }
}

// -------------------- fused SSM + gate (tf32-rounded output) ----------------
__global__ void __launch_bounds__(256) ssm_kernel(
    const float* __restrict__ xz, int ld,
    const float* __restrict__ dt,
    const float* __restrict__ coef,
    const float* __restrict__ A,
    float* __restrict__ gated)
{
    const int token = blockIdx.x;
    __shared__ float c[NSTATE];
    if (threadIdx.x < NSTATE) c[threadIdx.x] = coef[token * NSTATE + threadIdx.x];
    __syncthreads();

    const float* xs  = xz + (size_t)token * ld;
    const float* zp  = xs + DIM;
    const float* dtp = dt + (size_t)token * DIM;
    float* gp = gated + (size_t)token * DIM;

    for (int d = threadIdx.x; d < DIM; d += 256) {
        const float dtd = dtp[d];
        float s = 0.f;
        #pragma unroll
        for (int n = 0; n < NSTATE; n++)
            s += c[n] * __expf(A[n * DIM + d] * dtd);
        const float xv = xs[d];
        const float zv = zp[d];
        const float sig = 1.0f / (1.0f + __expf(-zv));
        gp[d] = to_tf32(s * xv * zv * sig);
    }
}

// -------------------- launch ------------------------------------------------
extern "C" void kernel_launch(void* const* d_in, const int* in_sizes, int n_in,
                              void* d_out, int out_size)
{
    const float* x        = (const float*)d_in[0];
    const float* ln_gamma = (const float*)d_in[1];
    const float* ln_beta  = (const float*)d_in[2];
    const float* W_in     = (const float*)d_in[3];
    const float* b_in     = (const float*)d_in[4];
    const float* state_A  = (const float*)d_in[5];
    const float* W_B      = (const float*)d_in[6];
    const float* b_B      = (const float*)d_in[7];
    const float* W_C      = (const float*)d_in[8];
    const float* b_C      = (const float*)d_in[9];
    const float* W_dt     = (const float*)d_in[10];
    const float* b_dt     = (const float*)d_in[11];
    const float* W_out    = (const float*)d_in[12];
    const float* b_out    = (const float*)d_in[13];
    float* out = (float*)d_out;

    float *xn, *xz, *dt, *gated, *coef, *win, *wdt, *wout;
    cudaGetSymbolAddress((void**)&xn,    g_xn);
    cudaGetSymbolAddress((void**)&xz,    g_xz);
    cudaGetSymbolAddress((void**)&dt,    g_dt);
    cudaGetSymbolAddress((void**)&gated, g_gated);
    cudaGetSymbolAddress((void**)&coef,  g_coef);
    cudaGetSymbolAddress((void**)&win,   g_win);
    cudaGetSymbolAddress((void**)&wdt,   g_wdt);
    cudaGetSymbolAddress((void**)&wout,  g_wout);

    // 0. round weights to tf32 (graph replays this; ~25us)
    round_kernel<<<1024, 256>>>((const float4*)W_in,  (float4*)win,  TWO_DIM * DIM / 4);
    round_kernel<<<512,  256>>>((const float4*)W_dt,  (float4*)wdt,  DIM * DIM / 4);
    round_kernel<<<512,  256>>>((const float4*)W_out, (float4*)wout, DIM * DIM / 4);

    // 1. LayerNorm (tf32 output)
    ln_kernel<<<TOKENS, 256>>>(x, ln_gamma, ln_beta, xn);

    // 2. xz = xn @ W_in^T + b_in   (M=4096, N=4096, K=2048), round output
    gemm_tf32<0, 1><<<dim3(TWO_DIM / BN, TOKENS / BM), 256>>>(
        xn, DIM, win, DIM, b_in, nullptr, 0, xz, TWO_DIM, DIM);

    // 3. dt = min(softplus(x_ssm @ W_dt^T + b_dt), 1)  (N=2048)
    gemm_tf32<1, 0><<<dim3(DIM / BN, TOKENS / BM), 256>>>(
        xz, TWO_DIM, wdt, DIM, b_dt, nullptr, 0, dt, DIM, DIM);

    // 4. coef = (x_ssm@W_B^T + b_B) * (x_ssm@W_C^T + b_C)
    bc_kernel<<<TOKENS, 256>>>(xz, TWO_DIM, W_B, b_B, W_C, b_C, coef);

    // 5. gated = (sum_n coef*exp(A*dt)) * x_ssm * silu(z)   (tf32 output)
    ssm_kernel<<<TOKENS, 256>>>(xz, TWO_DIM, dt, coef, state_A, gated);

    // 6. out = gated @ W_out^T + b_out + residual(x)
    gemm_tf32<2, 0><<<dim3(DIM / BN, TOKENS / BM), 256>>>(
        gated, DIM, wout, DIM, b_out, x, DIM, out, DIM, DIM);
}